// round 13
// baseline (speedup 1.0000x reference)
#include <cuda_runtime.h>
#include <cuda_fp16.h>
#include <cstdint>

// Problem constants
#define BATCH 4
#define SEQ   2048
#define CDIM  1024
#define HEADS 16
#define HDIM  64
#define BT    (BATCH * SEQ)       // 8192 rows
#define C3    (3 * CDIM)          // 3072

// Scratch in device globals (no dynamic allocation allowed)
__device__ __half g_qkv[(size_t)BT * C3];     // [B*T, 3C] fp16
__device__ __half g_y[(size_t)BT * CDIM];     // [B*T, C] attn out, fp16
__device__ __half g_xh[(size_t)BT * CDIM];    // x in fp16
__device__ __half g_wah[(size_t)C3 * CDIM];   // W_attn^T [3C][C] fp16
__device__ __half g_wph[(size_t)CDIM * CDIM]; // W_proj^T [C][C] fp16

// ---------------------------------------------------------------------------
// Helpers
// ---------------------------------------------------------------------------
__device__ __forceinline__ uint32_t smem_u32(const void* p) {
    uint32_t a;
    asm("{ .reg .u64 t; cvta.to.shared.u64 t, %1; cvt.u32.u64 %0, t; }"
        : "=r"(a) : "l"(p));
    return a;
}

__device__ __forceinline__ void mma16(float* c, const unsigned* a, const unsigned* b) {
    asm volatile(
        "mma.sync.aligned.m16n8k16.row.col.f32.f16.f16.f32 "
        "{%0,%1,%2,%3}, {%4,%5,%6,%7}, {%8,%9}, {%0,%1,%2,%3};"
        : "+f"(c[0]), "+f"(c[1]), "+f"(c[2]), "+f"(c[3])
        : "r"(a[0]), "r"(a[1]), "r"(a[2]), "r"(a[3]), "r"(b[0]), "r"(b[1]));
}

#define LDSM4(r0, r1, r2, r3, addr)                                           \
    asm volatile("ldmatrix.sync.aligned.m8n8.x4.shared.b16 {%0,%1,%2,%3}, [%4];" \
                 : "=r"(r0), "=r"(r1), "=r"(r2), "=r"(r3) : "r"(addr))

#define LDSM4T(r0, r1, r2, r3, addr)                                          \
    asm volatile("ldmatrix.sync.aligned.m8n8.x4.trans.shared.b16 {%0,%1,%2,%3}, [%4];" \
                 : "=r"(r0), "=r"(r1), "=r"(r2), "=r"(r3) : "r"(addr))

#define CP16(dst, src)                                                        \
    asm volatile("cp.async.cg.shared.global [%0], [%1], 16;"                  \
                 :: "r"(dst), "l"(src))
#define CP_COMMIT() asm volatile("cp.async.commit_group;" ::: "memory")
#define CP_WAIT(n)  asm volatile("cp.async.wait_group %0;" :: "n"(n) : "memory")

// ---------------------------------------------------------------------------
// Preprocessing: fp16 convert (and transpose for weights)
// ---------------------------------------------------------------------------
__global__ void tohalf_pass(const float* __restrict__ src, __half* __restrict__ dst) {
    const int i = blockIdx.x * blockDim.x + threadIdx.x;
    const float4 v = ((const float4*)src)[i];
    ((__half2*)dst)[2 * i + 0] = __floats2half2_rn(v.x, v.y);
    ((__half2*)dst)[2 * i + 1] = __floats2half2_rn(v.z, v.w);
}

// W[K][N] -> WT[N][K] in fp16
__global__ void wtrans(const float* __restrict__ W, __half* __restrict__ WT,
                       int K, int N) {
    __shared__ float t[32][33];
    const int n0 = blockIdx.x * 32, k0 = blockIdx.y * 32;
    const int tx = threadIdx.x, ty = threadIdx.y;
    #pragma unroll
    for (int j = 0; j < 4; j++)
        t[ty + 8 * j][tx] = W[(size_t)(k0 + ty + 8 * j) * N + n0 + tx];
    __syncthreads();
    #pragma unroll
    for (int j = 0; j < 4; j++)
        WT[(size_t)(n0 + ty + 8 * j) * K + k0 + tx] = __float2half_rn(t[tx][ty + 8 * j]);
}

// ---------------------------------------------------------------------------
// FP16 GEMM: C[M,N] = A[M,K] @ Bt[N,K]^T + bias[N]
// Block tile 128x256, K-chunk 64 (one 128B row), 512 threads = 16 warps (2x8),
// warp tile 64x32. cp.async 4-stage pipeline, ldmatrix, XOR-swizzled rows.
// ---------------------------------------------------------------------------
#define BM 128
#define BN 256
#define GSTAGE 49152           // 16KB A + 32KB B
#define GSB_OFF 16384
#define GEMM_SMEM (4 * GSTAGE) // 196608

__global__ __launch_bounds__(512, 1) void gemm_h(
    const __half* __restrict__ A, const __half* __restrict__ Bt,
    const float* __restrict__ bias, void* __restrict__ Cout,
    int M, int N, int K, int outHalf)
{
    extern __shared__ char sm[];
    const uint32_t sb = smem_u32(sm);
    const int tid  = threadIdx.x;
    const int lane = tid & 31;
    const int warp = tid >> 5;           // 0..15
    const int g    = lane >> 2;
    const int tg   = lane & 3;
    const int m0 = blockIdx.y * BM;
    const int n0 = blockIdx.x * BN;
    const int wm = (warp >> 3) * 64;     // 0 / 64
    const int wn = (warp & 7) * 32;      // 0..224

    // cp.async: thread t covers A rows (t>>3), (t>>3)+64; B rows +0,64,128,192
    const int ar  = tid >> 3;            // 0..63
    const int ach = tid & 7;
    const uint32_t sca = (uint32_t)((ach ^ (ar & 7)) * 16);
    const __half* aSrc = A  + (size_t)(m0 + ar) * K + ach * 8;
    const __half* bSrc = Bt + (size_t)(n0 + ar) * K + ach * 8;

    const uint32_t alr = lane & 7;
    const uint32_t aRowL = (lane & 7) + ((lane >> 3) & 1) * 8;
    const uint32_t aChL  = (lane >> 4);
    const uint32_t bRowL = (lane & 7) + ((lane >> 4) & 1) * 8;
    const uint32_t bChL  = (lane >> 3) & 1;

    float acc[4][4][4] = {};
    const int nch = K / 64;

    #pragma unroll
    for (int s = 0; s < 3; s++) {
        const uint32_t st = sb + s * GSTAGE;
        const int k0 = s * 64;
        #pragma unroll
        for (int j = 0; j < 2; j++)
            CP16(st + (uint32_t)(ar + 64 * j) * 128 + sca,
                 aSrc + k0 + (size_t)j * 64 * K);
        #pragma unroll
        for (int j = 0; j < 4; j++)
            CP16(st + GSB_OFF + (uint32_t)(ar + 64 * j) * 128 + sca,
                 bSrc + k0 + (size_t)j * 64 * K);
        CP_COMMIT();
    }

    for (int i = 0; i < nch; i++) {
        CP_WAIT(2);
        __syncthreads();

        if (i + 3 < nch) {
            const uint32_t st = sb + ((i + 3) & 3) * GSTAGE;
            const int k0 = (i + 3) * 64;
            #pragma unroll
            for (int j = 0; j < 2; j++)
                CP16(st + (uint32_t)(ar + 64 * j) * 128 + sca,
                     aSrc + k0 + (size_t)j * 64 * K);
            #pragma unroll
            for (int j = 0; j < 4; j++)
                CP16(st + GSB_OFF + (uint32_t)(ar + 64 * j) * 128 + sca,
                     bSrc + k0 + (size_t)j * 64 * K);
        }
        CP_COMMIT();

        const uint32_t stA = sb + (i & 3) * GSTAGE;
        const uint32_t stB = stA + GSB_OFF;
        #pragma unroll
        for (int ks = 0; ks < 4; ks++) {      // k16 steps
            unsigned af[4][4];
            #pragma unroll
            for (int mt = 0; mt < 4; mt++) {
                const uint32_t addr = stA
                    + (uint32_t)(wm + mt * 16 + aRowL) * 128
                    + (((2u * ks + aChL) ^ alr) * 16);
                LDSM4(af[mt][0], af[mt][1], af[mt][2], af[mt][3], addr);
            }
            unsigned bf[4][2];
            #pragma unroll
            for (int p = 0; p < 2; p++) {
                const uint32_t addr = stB
                    + (uint32_t)(wn + p * 16 + bRowL) * 128
                    + (((2u * ks + bChL) ^ alr) * 16);
                LDSM4(bf[2 * p][0], bf[2 * p][1], bf[2 * p + 1][0], bf[2 * p + 1][1], addr);
            }
            #pragma unroll
            for (int mt = 0; mt < 4; mt++)
                #pragma unroll
                for (int nt = 0; nt < 4; nt++)
                    mma16(acc[mt][nt], af[mt], bf[nt]);
        }
    }

    // epilogue
    #pragma unroll
    for (int mt = 0; mt < 4; mt++) {
        const int r0 = m0 + wm + mt * 16 + g;
        #pragma unroll
        for (int nt = 0; nt < 4; nt++) {
            const int c0 = n0 + wn + nt * 8 + tg * 2;
            const float b0v = bias[c0], b1v = bias[c0 + 1];
            const float v0 = acc[mt][nt][0] + b0v, v1 = acc[mt][nt][1] + b1v;
            const float v2 = acc[mt][nt][2] + b0v, v3 = acc[mt][nt][3] + b1v;
            if (outHalf) {
                __half* Ch = (__half*)Cout;
                *(__half2*)&Ch[(size_t)r0 * N + c0] = __floats2half2_rn(v0, v1);
                *(__half2*)&Ch[(size_t)(r0 + 8) * N + c0] = __floats2half2_rn(v2, v3);
            } else {
                float* Cf = (float*)Cout;
                *(float2*)&Cf[(size_t)r0 * N + c0] = make_float2(v0, v1);
                *(float2*)&Cf[(size_t)(r0 + 8) * N + c0] = make_float2(v2, v3);
            }
        }
    }
}

// ---------------------------------------------------------------------------
// Flash attention (causal), fp16 mma.sync, cp.async pipelined.
// Block = (128-row Q tile, head, batch). 256 threads = 8 warps;
// warp w owns q rows [w*16, w*16+16). KV tiles of 64 rows, double-buffered.
// SMEM rows: 64 halfs padded to 144B -> conflict-free, no swizzle.
// __launch_bounds__(256, 2): cap regs at 128 so 2 CTAs co-reside per SM.
// ---------------------------------------------------------------------------
#define ARS 144                         // attention smem row stride bytes
#define ATT_SP   0
#define ATT_K(s) (18432 + (s) * 9216)
#define ATT_V(s) (36864 + (s) * 9216)
#define ATT_SMEM 55296

__global__ __launch_bounds__(256, 2) void attn_h()
{
    extern __shared__ char attsm[];
    const uint32_t base = smem_u32(attsm);

    const int tid  = threadIdx.x;
    const int lane = tid & 31;
    const int warp = tid >> 5;
    const int g    = lane >> 2;
    const int tg   = lane & 3;

    const uint32_t aRowL = (lane & 7) + ((lane >> 3) & 1) * 8;
    const uint32_t aChL  = (lane >> 4);
    const uint32_t bRowL = (lane & 7) + ((lane >> 4) & 1) * 8;
    const uint32_t bChL  = (lane >> 3) & 1;

    const int qt = (gridDim.x - 1) - blockIdx.x;   // big tiles first
    const int h  = blockIdx.y;
    const int b  = blockIdx.z;
    const __half* qkv = g_qkv + (size_t)b * SEQ * C3;

    // cp.async: 64-row tile = 64 rows x 8 chunks of 16B
    const int r8 = tid >> 3;            // 0..31
    const int ch = tid & 7;             // 0..7

    // --- Load Q (128 rows) ---
    const __half* qsrc = qkv + (size_t)(qt * 128 + r8) * C3 + h * HDIM + ch * 8;
    #pragma unroll
    for (int j = 0; j < 4; j++)
        CP16(base + ATT_SP + (uint32_t)(r8 + 32 * j) * ARS + ch * 16,
             qsrc + (size_t)(32 * j) * C3);
    CP_COMMIT();

    const __half* ksrc = qkv + (size_t)r8 * C3 + CDIM     + h * HDIM + ch * 8;
    const __half* vsrc = qkv + (size_t)r8 * C3 + 2 * CDIM + h * HDIM + ch * 8;

    // --- Prefetch KV tile 0 ---
    #pragma unroll
    for (int j = 0; j < 2; j++) {
        CP16(base + ATT_K(0) + (uint32_t)(r8 + 32 * j) * ARS + ch * 16,
             ksrc + (size_t)(32 * j) * C3);
        CP16(base + ATT_V(0) + (uint32_t)(r8 + 32 * j) * ARS + ch * 16,
             vsrc + (size_t)(32 * j) * C3);
    }
    CP_COMMIT();

    CP_WAIT(1);
    __syncthreads();

    // --- Q fragments to registers ---
    unsigned aq[4][4];
    #pragma unroll
    for (int ks = 0; ks < 4; ks++)
        LDSM4(aq[ks][0], aq[ks][1], aq[ks][2], aq[ks][3],
              base + ATT_SP + (uint32_t)(warp * 16 + aRowL) * ARS
                            + (2u * ks + aChL) * 16);

    float o[8][4] = {};
    float mrun[2] = {-1e30f, -1e30f};
    float lrun[2] = {0.f, 0.f};
    const int rowA = qt * 128 + warp * 16 + g;
    const int qmax = qt * 128 + warp * 16 + 15;

    const int ntiles = 2 * qt + 2;
    for (int i = 0; i < ntiles; i++) {
        __syncthreads();
        if (i + 1 < ntiles) {
            const uint32_t kb = base + ATT_K((i + 1) & 1);
            const uint32_t vb = base + ATT_V((i + 1) & 1);
            const size_t roff = (size_t)(i + 1) * 64 * C3;
            #pragma unroll
            for (int j = 0; j < 2; j++) {
                CP16(kb + (uint32_t)(r8 + 32 * j) * ARS + ch * 16,
                     ksrc + roff + (size_t)(32 * j) * C3);
                CP16(vb + (uint32_t)(r8 + 32 * j) * ARS + ch * 16,
                     vsrc + roff + (size_t)(32 * j) * C3);
            }
            CP_COMMIT();
            CP_WAIT(1);
        } else {
            CP_WAIT(0);
        }
        __syncthreads();

        const int jbase = i * 64;
        if (jbase > qmax) continue;

        const uint32_t kb = base + ATT_K(i & 1);
        const uint32_t vb = base + ATT_V(i & 1);

        // S = Q @ K^T  (16 x 64 per warp)
        float s[8][4] = {};
        #pragma unroll
        for (int ks = 0; ks < 4; ks++) {
            unsigned bf[8][2];
            #pragma unroll
            for (int p = 0; p < 4; p++)
                LDSM4(bf[2 * p][0], bf[2 * p][1], bf[2 * p + 1][0], bf[2 * p + 1][1],
                      kb + (uint32_t)(p * 16 + bRowL) * ARS + (2u * ks + bChL) * 16);
            #pragma unroll
            for (int nt = 0; nt < 8; nt++)
                mma16(s[nt], aq[ks], bf[nt]);
        }

        #pragma unroll
        for (int nt = 0; nt < 8; nt++) {
            s[nt][0] *= 0.125f; s[nt][1] *= 0.125f;
            s[nt][2] *= 0.125f; s[nt][3] *= 0.125f;
        }

        if (i >= 2 * qt) {
            #pragma unroll
            for (int nt = 0; nt < 8; nt++) {
                const int c = jbase + nt * 8 + tg * 2;
                if (c     > rowA)     s[nt][0] = -1e30f;
                if (c + 1 > rowA)     s[nt][1] = -1e30f;
                if (c     > rowA + 8) s[nt][2] = -1e30f;
                if (c + 1 > rowA + 8) s[nt][3] = -1e30f;
            }
        }

        // online softmax
        float mA = -1e30f, mB = -1e30f;
        #pragma unroll
        for (int nt = 0; nt < 8; nt++) {
            mA = fmaxf(mA, fmaxf(s[nt][0], s[nt][1]));
            mB = fmaxf(mB, fmaxf(s[nt][2], s[nt][3]));
        }
        mA = fmaxf(mA, __shfl_xor_sync(0xffffffffu, mA, 1));
        mA = fmaxf(mA, __shfl_xor_sync(0xffffffffu, mA, 2));
        mB = fmaxf(mB, __shfl_xor_sync(0xffffffffu, mB, 1));
        mB = fmaxf(mB, __shfl_xor_sync(0xffffffffu, mB, 2));

        const float mnA = fmaxf(mrun[0], mA);
        const float mnB = fmaxf(mrun[1], mB);
        const float cA  = __expf(mrun[0] - mnA);
        const float cB  = __expf(mrun[1] - mnB);

        float sumA = 0.f, sumB = 0.f;
        __half* sph = (__half*)(attsm + ATT_SP);
        #pragma unroll
        for (int nt = 0; nt < 8; nt++) {
            const float p0 = __expf(s[nt][0] - mnA);
            const float p1 = __expf(s[nt][1] - mnA);
            const float p2 = __expf(s[nt][2] - mnB);
            const float p3 = __expf(s[nt][3] - mnB);
            sumA += p0 + p1;
            sumB += p2 + p3;
            const int col = nt * 8 + tg * 2;
            *(__half2*)&sph[(warp * 16 + g) * 72 + col]     = __floats2half2_rn(p0, p1);
            *(__half2*)&sph[(warp * 16 + g + 8) * 72 + col] = __floats2half2_rn(p2, p3);
            o[nt][0] *= cA; o[nt][1] *= cA;
            o[nt][2] *= cB; o[nt][3] *= cB;
        }
        sumA += __shfl_xor_sync(0xffffffffu, sumA, 1);
        sumA += __shfl_xor_sync(0xffffffffu, sumA, 2);
        sumB += __shfl_xor_sync(0xffffffffu, sumB, 1);
        sumB += __shfl_xor_sync(0xffffffffu, sumB, 2);
        lrun[0] = lrun[0] * cA + sumA;
        lrun[1] = lrun[1] * cB + sumB;
        mrun[0] = mnA;
        mrun[1] = mnB;

        __syncwarp();   // P STS -> LDSM (warp-private rows)

        // O += P @ V  (B frags via ldmatrix.trans from natural [j][d] V)
        #pragma unroll
        for (int ks = 0; ks < 4; ks++) {
            unsigned af[4];
            LDSM4(af[0], af[1], af[2], af[3],
                  base + ATT_SP + (uint32_t)(warp * 16 + aRowL) * ARS
                                + (2u * ks + aChL) * 16);
            unsigned bf[8][2];
            #pragma unroll
            for (int p = 0; p < 4; p++)
                LDSM4T(bf[2 * p][0], bf[2 * p][1], bf[2 * p + 1][0], bf[2 * p + 1][1],
                       vb + (uint32_t)(16 * ks + aRowL) * ARS + (2u * p + aChL) * 16);
            #pragma unroll
            for (int nt = 0; nt < 8; nt++)
                mma16(o[nt], af, bf[nt]);
        }
    }

    // epilogue: normalize, store fp16 y
    const float iA = 1.f / lrun[0];
    const float iB = 1.f / lrun[1];
    #pragma unroll
    for (int nt = 0; nt < 8; nt++) {
        const int col = h * HDIM + nt * 8 + tg * 2;
        *(__half2*)&g_y[(size_t)(b * SEQ + rowA) * CDIM + col] =
            __floats2half2_rn(o[nt][0] * iA, o[nt][1] * iA);
        *(__half2*)&g_y[(size_t)(b * SEQ + rowA + 8) * CDIM + col] =
            __floats2half2_rn(o[nt][2] * iB, o[nt][3] * iB);
    }
}

// ---------------------------------------------------------------------------
// Launch
// ---------------------------------------------------------------------------
extern "C" void kernel_launch(void* const* d_in, const int* in_sizes, int n_in,
                              void* d_out, int out_size)
{
    const float* x      = (const float*)d_in[0];  // [B,T,C]
    const float* W_attn = (const float*)d_in[1];  // [C,3C]
    const float* b_attn = (const float*)d_in[2];  // [3C]
    const float* W_proj = (const float*)d_in[3];  // [C,C]
    const float* b_proj = (const float*)d_in[4];  // [C]
    float* out = (float*)d_out;                   // [B,T,C]

    __half *qkv, *y, *xh, *wah, *wph;
    cudaGetSymbolAddress((void**)&qkv, g_qkv);
    cudaGetSymbolAddress((void**)&y,   g_y);
    cudaGetSymbolAddress((void**)&xh,  g_xh);
    cudaGetSymbolAddress((void**)&wah, g_wah);
    cudaGetSymbolAddress((void**)&wph, g_wph);

    cudaFuncSetAttribute(attn_h, cudaFuncAttributeMaxDynamicSharedMemorySize, ATT_SMEM);
    cudaFuncSetAttribute(gemm_h, cudaFuncAttributeMaxDynamicSharedMemorySize, GEMM_SMEM);

    // 0) Preprocess: convert x, transpose+convert weights
    tohalf_pass<<<(BT * CDIM) / (4 * 256), 256>>>(x, xh);
    wtrans<<<dim3(C3 / 32, CDIM / 32), dim3(32, 8)>>>(W_attn, wah, CDIM, C3);
    wtrans<<<dim3(CDIM / 32, CDIM / 32), dim3(32, 8)>>>(W_proj, wph, CDIM, CDIM);

    // 1) QKV projection -> fp16 qkv
    gemm_h<<<dim3(C3 / BN, BT / BM), 512, GEMM_SMEM>>>(xh, wah, b_attn, qkv,
                                                       BT, C3, CDIM, 1);
    // 2) Causal flash attention -> fp16 y
    attn_h<<<dim3(SEQ / 128, HEADS, BATCH), 256, ATT_SMEM>>>();

    // 3) Output projection -> fp32 out
    gemm_h<<<dim3(CDIM / BN, BT / BM), 512, GEMM_SMEM>>>(y, wph, b_proj, out,
                                                         BT, CDIM, CDIM, 0);
}

// round 14
// speedup vs baseline: 1.0773x; 1.0773x over previous
#include <cuda_runtime.h>
#include <cuda_fp16.h>
#include <cstdint>

// Problem constants
#define BATCH 4
#define SEQ   2048
#define CDIM  1024
#define HEADS 16
#define HDIM  64
#define BT    (BATCH * SEQ)       // 8192 rows
#define C3    (3 * CDIM)          // 3072

// Scratch in device globals (no dynamic allocation allowed)
__device__ __half g_qkv[(size_t)BT * C3];     // [B*T, 3C] fp16
__device__ __half g_y[(size_t)BT * CDIM];     // [B*T, C] attn out, fp16
__device__ __half g_xh[(size_t)BT * CDIM];    // x in fp16
__device__ __half g_wah[(size_t)C3 * CDIM];   // W_attn^T [3C][C] fp16
__device__ __half g_wph[(size_t)CDIM * CDIM]; // W_proj^T [C][C] fp16

// ---------------------------------------------------------------------------
// Helpers
// ---------------------------------------------------------------------------
__device__ __forceinline__ uint32_t smem_u32(const void* p) {
    uint32_t a;
    asm("{ .reg .u64 t; cvta.to.shared.u64 t, %1; cvt.u32.u64 %0, t; }"
        : "=r"(a) : "l"(p));
    return a;
}

__device__ __forceinline__ void mma16(float* c, const unsigned* a, const unsigned* b) {
    asm volatile(
        "mma.sync.aligned.m16n8k16.row.col.f32.f16.f16.f32 "
        "{%0,%1,%2,%3}, {%4,%5,%6,%7}, {%8,%9}, {%0,%1,%2,%3};"
        : "+f"(c[0]), "+f"(c[1]), "+f"(c[2]), "+f"(c[3])
        : "r"(a[0]), "r"(a[1]), "r"(a[2]), "r"(a[3]), "r"(b[0]), "r"(b[1]));
}

__device__ __forceinline__ unsigned h2u(float a, float b) {
    const __half2 h = __floats2half2_rn(a, b);
    return *(const unsigned*)&h;
}

#define LDSM4(r0, r1, r2, r3, addr)                                           \
    asm volatile("ldmatrix.sync.aligned.m8n8.x4.shared.b16 {%0,%1,%2,%3}, [%4];" \
                 : "=r"(r0), "=r"(r1), "=r"(r2), "=r"(r3) : "r"(addr))

#define LDSM4T(r0, r1, r2, r3, addr)                                          \
    asm volatile("ldmatrix.sync.aligned.m8n8.x4.trans.shared.b16 {%0,%1,%2,%3}, [%4];" \
                 : "=r"(r0), "=r"(r1), "=r"(r2), "=r"(r3) : "r"(addr))

#define CP16(dst, src)                                                        \
    asm volatile("cp.async.cg.shared.global [%0], [%1], 16;"                  \
                 :: "r"(dst), "l"(src))
#define CP_COMMIT() asm volatile("cp.async.commit_group;" ::: "memory")
#define CP_WAIT(n)  asm volatile("cp.async.wait_group %0;" :: "n"(n) : "memory")

// ---------------------------------------------------------------------------
// Preprocessing: fp16 convert (and transpose for weights)
// ---------------------------------------------------------------------------
__global__ void tohalf_pass(const float* __restrict__ src, __half* __restrict__ dst) {
    const int i = blockIdx.x * blockDim.x + threadIdx.x;
    const float4 v = ((const float4*)src)[i];
    ((__half2*)dst)[2 * i + 0] = __floats2half2_rn(v.x, v.y);
    ((__half2*)dst)[2 * i + 1] = __floats2half2_rn(v.z, v.w);
}

// W[K][N] -> WT[N][K] in fp16
__global__ void wtrans(const float* __restrict__ W, __half* __restrict__ WT,
                       int K, int N) {
    __shared__ float t[32][33];
    const int n0 = blockIdx.x * 32, k0 = blockIdx.y * 32;
    const int tx = threadIdx.x, ty = threadIdx.y;
    #pragma unroll
    for (int j = 0; j < 4; j++)
        t[ty + 8 * j][tx] = W[(size_t)(k0 + ty + 8 * j) * N + n0 + tx];
    __syncthreads();
    #pragma unroll
    for (int j = 0; j < 4; j++)
        WT[(size_t)(n0 + ty + 8 * j) * K + k0 + tx] = __float2half_rn(t[tx][ty + 8 * j]);
}

// ---------------------------------------------------------------------------
// FP16 GEMM (R10 config — at the mma.sync pipe floor, do not touch):
// C[M,N] = A[M,K] @ Bt[N,K]^T + bias[N]
// Block tile 128x256, K-chunk 64, 256 threads = 8 warps (2x4), warp 64x64.
// ---------------------------------------------------------------------------
#define BM 128
#define BN 256
#define GSTAGE 49152           // 16KB A + 32KB B
#define GSB_OFF 16384
#define GEMM_SMEM (4 * GSTAGE) // 196608

__global__ __launch_bounds__(256, 1) void gemm_h(
    const __half* __restrict__ A, const __half* __restrict__ Bt,
    const float* __restrict__ bias, void* __restrict__ Cout,
    int M, int N, int K, int outHalf)
{
    extern __shared__ char sm[];
    const uint32_t sb = smem_u32(sm);
    const int tid  = threadIdx.x;
    const int lane = tid & 31;
    const int warp = tid >> 5;
    const int g    = lane >> 2;
    const int tg   = lane & 3;
    const int m0 = blockIdx.y * BM;
    const int n0 = blockIdx.x * BN;
    const int wm = (warp >> 2) * 64;
    const int wn = (warp & 3) * 64;

    const int ar  = tid >> 3;
    const int ach = tid & 7;
    const uint32_t sca = (uint32_t)((ach ^ (ar & 7)) * 16);
    const __half* aSrc = A  + (size_t)(m0 + ar) * K + ach * 8;
    const __half* bSrc = Bt + (size_t)(n0 + ar) * K + ach * 8;

    const uint32_t alr = lane & 7;
    const uint32_t aRowL = (lane & 7) + ((lane >> 3) & 1) * 8;
    const uint32_t aChL  = (lane >> 4);
    const uint32_t bRowL = (lane & 7) + ((lane >> 4) & 1) * 8;
    const uint32_t bChL  = (lane >> 3) & 1;

    float acc[4][8][4] = {};
    const int nch = K / 64;

    #pragma unroll
    for (int s = 0; s < 3; s++) {
        const uint32_t st = sb + s * GSTAGE;
        const int k0 = s * 64;
        #pragma unroll
        for (int j = 0; j < 4; j++)
            CP16(st + (uint32_t)(ar + 32 * j) * 128 + sca,
                 aSrc + k0 + (size_t)j * 32 * K);
        #pragma unroll
        for (int j = 0; j < 8; j++)
            CP16(st + GSB_OFF + (uint32_t)(ar + 32 * j) * 128 + sca,
                 bSrc + k0 + (size_t)j * 32 * K);
        CP_COMMIT();
    }

    for (int i = 0; i < nch; i++) {
        CP_WAIT(2);
        __syncthreads();

        if (i + 3 < nch) {
            const uint32_t st = sb + ((i + 3) & 3) * GSTAGE;
            const int k0 = (i + 3) * 64;
            #pragma unroll
            for (int j = 0; j < 4; j++)
                CP16(st + (uint32_t)(ar + 32 * j) * 128 + sca,
                     aSrc + k0 + (size_t)j * 32 * K);
            #pragma unroll
            for (int j = 0; j < 8; j++)
                CP16(st + GSB_OFF + (uint32_t)(ar + 32 * j) * 128 + sca,
                     bSrc + k0 + (size_t)j * 32 * K);
        }
        CP_COMMIT();

        const uint32_t stA = sb + (i & 3) * GSTAGE;
        const uint32_t stB = stA + GSB_OFF;
        #pragma unroll
        for (int ks = 0; ks < 4; ks++) {
            unsigned af[4][4];
            #pragma unroll
            for (int mt = 0; mt < 4; mt++) {
                const uint32_t addr = stA
                    + (uint32_t)(wm + mt * 16 + aRowL) * 128
                    + (((2u * ks + aChL) ^ alr) * 16);
                LDSM4(af[mt][0], af[mt][1], af[mt][2], af[mt][3], addr);
            }
            unsigned bf[8][2];
            #pragma unroll
            for (int p = 0; p < 4; p++) {
                const uint32_t addr = stB
                    + (uint32_t)(wn + p * 16 + bRowL) * 128
                    + (((2u * ks + bChL) ^ alr) * 16);
                LDSM4(bf[2 * p][0], bf[2 * p][1], bf[2 * p + 1][0], bf[2 * p + 1][1], addr);
            }
            #pragma unroll
            for (int mt = 0; mt < 4; mt++)
                #pragma unroll
                for (int nt = 0; nt < 8; nt++)
                    mma16(acc[mt][nt], af[mt], bf[nt]);
        }
    }

    #pragma unroll
    for (int mt = 0; mt < 4; mt++) {
        const int r0 = m0 + wm + mt * 16 + g;
        #pragma unroll
        for (int nt = 0; nt < 8; nt++) {
            const int c0 = n0 + wn + nt * 8 + tg * 2;
            const float b0v = bias[c0], b1v = bias[c0 + 1];
            const float v0 = acc[mt][nt][0] + b0v, v1 = acc[mt][nt][1] + b1v;
            const float v2 = acc[mt][nt][2] + b0v, v3 = acc[mt][nt][3] + b1v;
            if (outHalf) {
                __half* Ch = (__half*)Cout;
                *(__half2*)&Ch[(size_t)r0 * N + c0] = __floats2half2_rn(v0, v1);
                *(__half2*)&Ch[(size_t)(r0 + 8) * N + c0] = __floats2half2_rn(v2, v3);
            } else {
                float* Cf = (float*)Cout;
                *(float2*)&Cf[(size_t)r0 * N + c0] = make_float2(v0, v1);
                *(float2*)&Cf[(size_t)(r0 + 8) * N + c0] = make_float2(v2, v3);
            }
        }
    }
}

// ---------------------------------------------------------------------------
// Flash attention (causal), fp16 mma.sync, cp.async pipelined.
// Block = (128-row Q tile, head, batch). 256 threads = 8 warps.
// P never touches SMEM: S-accumulator fragments are repacked in registers
// into the PV A-operand layout (FA2 trick). Softmax in exp2 domain.
// 2 CTAs/SM via __launch_bounds__(256, 2).
// ---------------------------------------------------------------------------
#define ARS 144                         // attention smem row stride bytes
#define ATT_SP   0
#define ATT_K(s) (18432 + (s) * 9216)
#define ATT_V(s) (36864 + (s) * 9216)
#define ATT_SMEM 55296
#define SCL2E 0.1803368801111204f      // 0.125 * log2(e)

__global__ __launch_bounds__(256, 2) void attn_h()
{
    extern __shared__ char attsm[];
    const uint32_t base = smem_u32(attsm);

    const int tid  = threadIdx.x;
    const int lane = tid & 31;
    const int warp = tid >> 5;
    const int g    = lane >> 2;
    const int tg   = lane & 3;

    const uint32_t aRowL = (lane & 7) + ((lane >> 3) & 1) * 8;
    const uint32_t aChL  = (lane >> 4);
    const uint32_t bRowL = (lane & 7) + ((lane >> 4) & 1) * 8;
    const uint32_t bChL  = (lane >> 3) & 1;

    const int qt = (gridDim.x - 1) - blockIdx.x;   // big tiles first
    const int h  = blockIdx.y;
    const int b  = blockIdx.z;
    const __half* qkv = g_qkv + (size_t)b * SEQ * C3;

    const int r8 = tid >> 3;            // 0..31
    const int ch = tid & 7;             // 0..7

    // --- Load Q (128 rows) ---
    const __half* qsrc = qkv + (size_t)(qt * 128 + r8) * C3 + h * HDIM + ch * 8;
    #pragma unroll
    for (int j = 0; j < 4; j++)
        CP16(base + ATT_SP + (uint32_t)(r8 + 32 * j) * ARS + ch * 16,
             qsrc + (size_t)(32 * j) * C3);
    CP_COMMIT();

    const __half* ksrc = qkv + (size_t)r8 * C3 + CDIM     + h * HDIM + ch * 8;
    const __half* vsrc = qkv + (size_t)r8 * C3 + 2 * CDIM + h * HDIM + ch * 8;

    // --- Prefetch KV tile 0 ---
    #pragma unroll
    for (int j = 0; j < 2; j++) {
        CP16(base + ATT_K(0) + (uint32_t)(r8 + 32 * j) * ARS + ch * 16,
             ksrc + (size_t)(32 * j) * C3);
        CP16(base + ATT_V(0) + (uint32_t)(r8 + 32 * j) * ARS + ch * 16,
             vsrc + (size_t)(32 * j) * C3);
    }
    CP_COMMIT();

    CP_WAIT(1);
    __syncthreads();

    // --- Q fragments to registers ---
    unsigned aq[4][4];
    #pragma unroll
    for (int ks = 0; ks < 4; ks++)
        LDSM4(aq[ks][0], aq[ks][1], aq[ks][2], aq[ks][3],
              base + ATT_SP + (uint32_t)(warp * 16 + aRowL) * ARS
                            + (2u * ks + aChL) * 16);

    float o[8][4] = {};
    float mrun[2] = {-1e30f, -1e30f};
    float lrun[2] = {0.f, 0.f};
    const int rowA = qt * 128 + warp * 16 + g;
    const int qmax = qt * 128 + warp * 16 + 15;

    const int ntiles = 2 * qt + 2;
    for (int i = 0; i < ntiles; i++) {
        __syncthreads();
        if (i + 1 < ntiles) {
            const uint32_t kb = base + ATT_K((i + 1) & 1);
            const uint32_t vb = base + ATT_V((i + 1) & 1);
            const size_t roff = (size_t)(i + 1) * 64 * C3;
            #pragma unroll
            for (int j = 0; j < 2; j++) {
                CP16(kb + (uint32_t)(r8 + 32 * j) * ARS + ch * 16,
                     ksrc + roff + (size_t)(32 * j) * C3);
                CP16(vb + (uint32_t)(r8 + 32 * j) * ARS + ch * 16,
                     vsrc + roff + (size_t)(32 * j) * C3);
            }
            CP_COMMIT();
            CP_WAIT(1);
        } else {
            CP_WAIT(0);
        }
        __syncthreads();

        const int jbase = i * 64;
        if (jbase > qmax) continue;

        const uint32_t kb = base + ATT_K(i & 1);
        const uint32_t vb = base + ATT_V(i & 1);

        // S = Q @ K^T  (16 x 64 per warp)
        float s[8][4] = {};
        #pragma unroll
        for (int ks = 0; ks < 4; ks++) {
            unsigned bf[8][2];
            #pragma unroll
            for (int p = 0; p < 4; p++)
                LDSM4(bf[2 * p][0], bf[2 * p][1], bf[2 * p + 1][0], bf[2 * p + 1][1],
                      kb + (uint32_t)(p * 16 + bRowL) * ARS + (2u * ks + bChL) * 16);
            #pragma unroll
            for (int nt = 0; nt < 8; nt++)
                mma16(s[nt], aq[ks], bf[nt]);
        }

        // scale into exp2 domain: s * (1/sqrt(D)) * log2(e)
        #pragma unroll
        for (int nt = 0; nt < 8; nt++) {
            s[nt][0] *= SCL2E; s[nt][1] *= SCL2E;
            s[nt][2] *= SCL2E; s[nt][3] *= SCL2E;
        }

        if (i >= 2 * qt) {
            #pragma unroll
            for (int nt = 0; nt < 8; nt++) {
                const int c = jbase + nt * 8 + tg * 2;
                if (c     > rowA)     s[nt][0] = -1e30f;
                if (c + 1 > rowA)     s[nt][1] = -1e30f;
                if (c     > rowA + 8) s[nt][2] = -1e30f;
                if (c + 1 > rowA + 8) s[nt][3] = -1e30f;
            }
        }

        // online softmax (base-2)
        float mA = -1e30f, mB = -1e30f;
        #pragma unroll
        for (int nt = 0; nt < 8; nt++) {
            mA = fmaxf(mA, fmaxf(s[nt][0], s[nt][1]));
            mB = fmaxf(mB, fmaxf(s[nt][2], s[nt][3]));
        }
        mA = fmaxf(mA, __shfl_xor_sync(0xffffffffu, mA, 1));
        mA = fmaxf(mA, __shfl_xor_sync(0xffffffffu, mA, 2));
        mB = fmaxf(mB, __shfl_xor_sync(0xffffffffu, mB, 1));
        mB = fmaxf(mB, __shfl_xor_sync(0xffffffffu, mB, 2));

        const float mnA = fmaxf(mrun[0], mA);
        const float mnB = fmaxf(mrun[1], mB);
        const float cA  = exp2f(mrun[0] - mnA);
        const float cB  = exp2f(mrun[1] - mnB);

        float sumA = 0.f, sumB = 0.f;
        unsigned ph[8][2];      // P in fp16 A-operand pairs
        #pragma unroll
        for (int nt = 0; nt < 8; nt++) {
            const float p0 = exp2f(s[nt][0] - mnA);
            const float p1 = exp2f(s[nt][1] - mnA);
            const float p2 = exp2f(s[nt][2] - mnB);
            const float p3 = exp2f(s[nt][3] - mnB);
            sumA += p0 + p1;
            sumB += p2 + p3;
            ph[nt][0] = h2u(p0, p1);
            ph[nt][1] = h2u(p2, p3);
            o[nt][0] *= cA; o[nt][1] *= cA;
            o[nt][2] *= cB; o[nt][3] *= cB;
        }
        sumA += __shfl_xor_sync(0xffffffffu, sumA, 1);
        sumA += __shfl_xor_sync(0xffffffffu, sumA, 2);
        sumB += __shfl_xor_sync(0xffffffffu, sumB, 1);
        sumB += __shfl_xor_sync(0xffffffffu, sumB, 2);
        lrun[0] = lrun[0] * cA + sumA;
        lrun[1] = lrun[1] * cB + sumB;
        mrun[0] = mnA;
        mrun[1] = mnB;

        // O += P @ V  (A = repacked S fragments; B via ldmatrix.trans of V)
        #pragma unroll
        for (int ks = 0; ks < 4; ks++) {
            const unsigned af[4] = { ph[2 * ks][0], ph[2 * ks][1],
                                     ph[2 * ks + 1][0], ph[2 * ks + 1][1] };
            unsigned bf[8][2];
            #pragma unroll
            for (int p = 0; p < 4; p++)
                LDSM4T(bf[2 * p][0], bf[2 * p][1], bf[2 * p + 1][0], bf[2 * p + 1][1],
                       vb + (uint32_t)(16 * ks + aRowL) * ARS + (2u * p + aChL) * 16);
            #pragma unroll
            for (int nt = 0; nt < 8; nt++)
                mma16(o[nt], af, bf[nt]);
        }
    }

    // epilogue: normalize, store fp16 y
    const float iA = 1.f / lrun[0];
    const float iB = 1.f / lrun[1];
    #pragma unroll
    for (int nt = 0; nt < 8; nt++) {
        const int col = h * HDIM + nt * 8 + tg * 2;
        *(__half2*)&g_y[(size_t)(b * SEQ + rowA) * CDIM + col] =
            __floats2half2_rn(o[nt][0] * iA, o[nt][1] * iA);
        *(__half2*)&g_y[(size_t)(b * SEQ + rowA + 8) * CDIM + col] =
            __floats2half2_rn(o[nt][2] * iB, o[nt][3] * iB);
    }
}

// ---------------------------------------------------------------------------
// Launch
// ---------------------------------------------------------------------------
extern "C" void kernel_launch(void* const* d_in, const int* in_sizes, int n_in,
                              void* d_out, int out_size)
{
    const float* x      = (const float*)d_in[0];  // [B,T,C]
    const float* W_attn = (const float*)d_in[1];  // [C,3C]
    const float* b_attn = (const float*)d_in[2];  // [3C]
    const float* W_proj = (const float*)d_in[3];  // [C,C]
    const float* b_proj = (const float*)d_in[4];  // [C]
    float* out = (float*)d_out;                   // [B,T,C]

    __half *qkv, *y, *xh, *wah, *wph;
    cudaGetSymbolAddress((void**)&qkv, g_qkv);
    cudaGetSymbolAddress((void**)&y,   g_y);
    cudaGetSymbolAddress((void**)&xh,  g_xh);
    cudaGetSymbolAddress((void**)&wah, g_wah);
    cudaGetSymbolAddress((void**)&wph, g_wph);

    cudaFuncSetAttribute(attn_h, cudaFuncAttributeMaxDynamicSharedMemorySize, ATT_SMEM);
    cudaFuncSetAttribute(gemm_h, cudaFuncAttributeMaxDynamicSharedMemorySize, GEMM_SMEM);

    // 0) Preprocess: convert x, transpose+convert weights
    tohalf_pass<<<(BT * CDIM) / (4 * 256), 256>>>(x, xh);
    wtrans<<<dim3(C3 / 32, CDIM / 32), dim3(32, 8)>>>(W_attn, wah, CDIM, C3);
    wtrans<<<dim3(CDIM / 32, CDIM / 32), dim3(32, 8)>>>(W_proj, wph, CDIM, CDIM);

    // 1) QKV projection -> fp16 qkv
    gemm_h<<<dim3(C3 / BN, BT / BM), 256, GEMM_SMEM>>>(xh, wah, b_attn, qkv,
                                                       BT, C3, CDIM, 1);
    // 2) Causal flash attention -> fp16 y
    attn_h<<<dim3(SEQ / 128, HEADS, BATCH), 256, ATT_SMEM>>>();

    // 3) Output projection -> fp32 out
    gemm_h<<<dim3(CDIM / BN, BT / BM), 256, GEMM_SMEM>>>(y, wph, b_proj, out,
                                                         BT, CDIM, CDIM, 0);
}

// round 15
// speedup vs baseline: 1.1269x; 1.0461x over previous
#include <cuda_runtime.h>
#include <cuda_fp16.h>
#include <cstdint>

// Problem constants
#define BATCH 4
#define SEQ   2048
#define CDIM  1024
#define HEADS 16
#define HDIM  64
#define BT    (BATCH * SEQ)       // 8192 rows
#define C3    (3 * CDIM)          // 3072

#define SCL2E 0.1803368801111204f // 0.125 * log2(e), folded into q at QKV epilogue

// Scratch in device globals (no dynamic allocation allowed)
__device__ __half g_qkv[(size_t)BT * C3];     // [B*T, 3C] fp16 (q pre-scaled)
__device__ __half g_y[(size_t)BT * CDIM];     // [B*T, C] attn out, fp16
__device__ __half g_xh[(size_t)BT * CDIM];    // x in fp16
__device__ __half g_wah[(size_t)C3 * CDIM];   // W_attn^T [3C][C] fp16
__device__ __half g_wph[(size_t)CDIM * CDIM]; // W_proj^T [C][C] fp16

// ---------------------------------------------------------------------------
// Helpers
// ---------------------------------------------------------------------------
__device__ __forceinline__ uint32_t smem_u32(const void* p) {
    uint32_t a;
    asm("{ .reg .u64 t; cvta.to.shared.u64 t, %1; cvt.u32.u64 %0, t; }"
        : "=r"(a) : "l"(p));
    return a;
}

__device__ __forceinline__ void mma16(float* c, const unsigned* a, const unsigned* b) {
    asm volatile(
        "mma.sync.aligned.m16n8k16.row.col.f32.f16.f16.f32 "
        "{%0,%1,%2,%3}, {%4,%5,%6,%7}, {%8,%9}, {%0,%1,%2,%3};"
        : "+f"(c[0]), "+f"(c[1]), "+f"(c[2]), "+f"(c[3])
        : "r"(a[0]), "r"(a[1]), "r"(a[2]), "r"(a[3]), "r"(b[0]), "r"(b[1]));
}

__device__ __forceinline__ unsigned h2u(float a, float b) {
    const __half2 h = __floats2half2_rn(a, b);
    return *(const unsigned*)&h;
}

#define LDSM4(r0, r1, r2, r3, addr)                                           \
    asm volatile("ldmatrix.sync.aligned.m8n8.x4.shared.b16 {%0,%1,%2,%3}, [%4];" \
                 : "=r"(r0), "=r"(r1), "=r"(r2), "=r"(r3) : "r"(addr))

#define LDSM4T(r0, r1, r2, r3, addr)                                          \
    asm volatile("ldmatrix.sync.aligned.m8n8.x4.trans.shared.b16 {%0,%1,%2,%3}, [%4];" \
                 : "=r"(r0), "=r"(r1), "=r"(r2), "=r"(r3) : "r"(addr))

#define CP16(dst, src)                                                        \
    asm volatile("cp.async.cg.shared.global [%0], [%1], 16;"                  \
                 :: "r"(dst), "l"(src))
#define CP_COMMIT() asm volatile("cp.async.commit_group;" ::: "memory")
#define CP_WAIT(n)  asm volatile("cp.async.wait_group %0;" :: "n"(n) : "memory")

// ---------------------------------------------------------------------------
// Preprocessing: fp16 convert (and transpose for weights)
// ---------------------------------------------------------------------------
__global__ void tohalf_pass(const float* __restrict__ src, __half* __restrict__ dst) {
    const int i = blockIdx.x * blockDim.x + threadIdx.x;
    const float4 v = ((const float4*)src)[i];
    ((__half2*)dst)[2 * i + 0] = __floats2half2_rn(v.x, v.y);
    ((__half2*)dst)[2 * i + 1] = __floats2half2_rn(v.z, v.w);
}

// W[K][N] -> WT[N][K] in fp16
__global__ void wtrans(const float* __restrict__ W, __half* __restrict__ WT,
                       int K, int N) {
    __shared__ float t[32][33];
    const int n0 = blockIdx.x * 32, k0 = blockIdx.y * 32;
    const int tx = threadIdx.x, ty = threadIdx.y;
    #pragma unroll
    for (int j = 0; j < 4; j++)
        t[ty + 8 * j][tx] = W[(size_t)(k0 + ty + 8 * j) * N + n0 + tx];
    __syncthreads();
    #pragma unroll
    for (int j = 0; j < 4; j++)
        WT[(size_t)(n0 + ty + 8 * j) * K + k0 + tx] = __float2half_rn(t[tx][ty + 8 * j]);
}

// ---------------------------------------------------------------------------
// FP16 GEMM (templated on BN): C[M,N] = A[M,K] @ Bt[N,K]^T + bias[N]
// Block tile 128 x BN_T, K-chunk 64, 256 threads = 8 warps (2x4),
// warp tile 64 x (BN_T/4). cp.async 4-stage pipeline, ldmatrix, XOR swizzle.
// scaleQ: multiply output columns < CDIM by SCL2E (QKV call only).
// ---------------------------------------------------------------------------
#define BM 128

template <int BN_T>
__global__ __launch_bounds__(256, 1) void gemm_h(
    const __half* __restrict__ A, const __half* __restrict__ Bt,
    const float* __restrict__ bias, void* __restrict__ Cout,
    int M, int N, int K, int outHalf, int scaleQ)
{
    constexpr int WN     = BN_T / 4;        // warp N tile (48 or 64)
    constexpr int NT     = WN / 8;          // n fragments (6 or 8)
    constexpr int PB     = WN / 16;         // B ldmatrix iters (3 or 4)
    constexpr int BLOADS = BN_T / 32;       // B cp.async iters (6 or 8)
    constexpr int GSB    = 16384;           // A bytes per stage
    constexpr int STAGE  = GSB + BN_T * 128;

    extern __shared__ char sm[];
    const uint32_t sb = smem_u32(sm);
    const int tid  = threadIdx.x;
    const int lane = tid & 31;
    const int warp = tid >> 5;
    const int g    = lane >> 2;
    const int tg   = lane & 3;
    const int m0 = blockIdx.y * BM;
    const int n0 = blockIdx.x * BN_T;
    const int wm = (warp >> 2) * 64;
    const int wn = (warp & 3) * WN;

    const int ar  = tid >> 3;
    const int ach = tid & 7;
    const uint32_t sca = (uint32_t)((ach ^ (ar & 7)) * 16);
    const __half* aSrc = A  + (size_t)(m0 + ar) * K + ach * 8;
    const __half* bSrc = Bt + (size_t)(n0 + ar) * K + ach * 8;

    const uint32_t alr = lane & 7;
    const uint32_t aRowL = (lane & 7) + ((lane >> 3) & 1) * 8;
    const uint32_t aChL  = (lane >> 4);
    const uint32_t bRowL = (lane & 7) + ((lane >> 4) & 1) * 8;
    const uint32_t bChL  = (lane >> 3) & 1;

    float acc[4][NT][4] = {};
    const int nch = K / 64;

    #pragma unroll
    for (int s = 0; s < 3; s++) {
        const uint32_t st = sb + s * STAGE;
        const int k0 = s * 64;
        #pragma unroll
        for (int j = 0; j < 4; j++)
            CP16(st + (uint32_t)(ar + 32 * j) * 128 + sca,
                 aSrc + k0 + (size_t)j * 32 * K);
        #pragma unroll
        for (int j = 0; j < BLOADS; j++)
            CP16(st + GSB + (uint32_t)(ar + 32 * j) * 128 + sca,
                 bSrc + k0 + (size_t)j * 32 * K);
        CP_COMMIT();
    }

    for (int i = 0; i < nch; i++) {
        CP_WAIT(2);
        __syncthreads();

        if (i + 3 < nch) {
            const uint32_t st = sb + ((i + 3) & 3) * STAGE;
            const int k0 = (i + 3) * 64;
            #pragma unroll
            for (int j = 0; j < 4; j++)
                CP16(st + (uint32_t)(ar + 32 * j) * 128 + sca,
                     aSrc + k0 + (size_t)j * 32 * K);
            #pragma unroll
            for (int j = 0; j < BLOADS; j++)
                CP16(st + GSB + (uint32_t)(ar + 32 * j) * 128 + sca,
                     bSrc + k0 + (size_t)j * 32 * K);
        }
        CP_COMMIT();

        const uint32_t stA = sb + (i & 3) * STAGE;
        const uint32_t stB = stA + GSB;
        #pragma unroll
        for (int ks = 0; ks < 4; ks++) {
            unsigned af[4][4];
            #pragma unroll
            for (int mt = 0; mt < 4; mt++) {
                const uint32_t addr = stA
                    + (uint32_t)(wm + mt * 16 + aRowL) * 128
                    + (((2u * ks + aChL) ^ alr) * 16);
                LDSM4(af[mt][0], af[mt][1], af[mt][2], af[mt][3], addr);
            }
            unsigned bf[NT][2];
            #pragma unroll
            for (int p = 0; p < PB; p++) {
                const uint32_t addr = stB
                    + (uint32_t)(wn + p * 16 + bRowL) * 128
                    + (((2u * ks + bChL) ^ alr) * 16);
                LDSM4(bf[2 * p][0], bf[2 * p][1], bf[2 * p + 1][0], bf[2 * p + 1][1], addr);
            }
            #pragma unroll
            for (int mt = 0; mt < 4; mt++)
                #pragma unroll
                for (int nt = 0; nt < NT; nt++)
                    mma16(acc[mt][nt], af[mt], bf[nt]);
        }
    }

    #pragma unroll
    for (int mt = 0; mt < 4; mt++) {
        const int r0 = m0 + wm + mt * 16 + g;
        #pragma unroll
        for (int nt = 0; nt < NT; nt++) {
            const int c0 = n0 + wn + nt * 8 + tg * 2;
            // q-prescale: nt blocks are 8-aligned and CDIM % 8 == 0, so the
            // block is entirely inside or outside the q column range.
            const float qs = (scaleQ && (n0 + wn + nt * 8) < CDIM) ? SCL2E : 1.0f;
            const float b0v = bias[c0], b1v = bias[c0 + 1];
            const float v0 = (acc[mt][nt][0] + b0v) * qs;
            const float v1 = (acc[mt][nt][1] + b1v) * qs;
            const float v2 = (acc[mt][nt][2] + b0v) * qs;
            const float v3 = (acc[mt][nt][3] + b1v) * qs;
            if (outHalf) {
                __half* Ch = (__half*)Cout;
                *(__half2*)&Ch[(size_t)r0 * N + c0] = __floats2half2_rn(v0, v1);
                *(__half2*)&Ch[(size_t)(r0 + 8) * N + c0] = __floats2half2_rn(v2, v3);
            } else {
                float* Cf = (float*)Cout;
                *(float2*)&Cf[(size_t)r0 * N + c0] = make_float2(v0, v1);
                *(float2*)&Cf[(size_t)(r0 + 8) * N + c0] = make_float2(v2, v3);
            }
        }
    }
}

#define QKV_BN   192
#define QKV_SMEM (4 * (16384 + QKV_BN * 128))  // 163840
#define PRJ_BN   256
#define PRJ_SMEM (4 * (16384 + PRJ_BN * 128))  // 196608

// ---------------------------------------------------------------------------
// Flash attention (causal), fp16 mma.sync, cp.async pipelined.
// Block = (128-row Q tile, head, batch). 256 threads = 8 warps.
// q arrives pre-scaled by 0.125*log2(e); softmax in exp2 domain.
// P stays in registers (S-frag -> A-frag repack). 2 CTAs/SM.
// ---------------------------------------------------------------------------
#define ARS 144                         // attention smem row stride bytes
#define ATT_SP   0
#define ATT_K(s) (18432 + (s) * 9216)
#define ATT_V(s) (36864 + (s) * 9216)
#define ATT_SMEM 55296

__global__ __launch_bounds__(256, 2) void attn_h()
{
    extern __shared__ char attsm[];
    const uint32_t base = smem_u32(attsm);

    const int tid  = threadIdx.x;
    const int lane = tid & 31;
    const int warp = tid >> 5;
    const int g    = lane >> 2;
    const int tg   = lane & 3;

    const uint32_t aRowL = (lane & 7) + ((lane >> 3) & 1) * 8;
    const uint32_t aChL  = (lane >> 4);
    const uint32_t bRowL = (lane & 7) + ((lane >> 4) & 1) * 8;
    const uint32_t bChL  = (lane >> 3) & 1;

    const int qt = (gridDim.x - 1) - blockIdx.x;   // big tiles first
    const int h  = blockIdx.y;
    const int b  = blockIdx.z;
    const __half* qkv = g_qkv + (size_t)b * SEQ * C3;

    const int r8 = tid >> 3;            // 0..31
    const int ch = tid & 7;             // 0..7

    // --- Load Q (128 rows, pre-scaled) ---
    const __half* qsrc = qkv + (size_t)(qt * 128 + r8) * C3 + h * HDIM + ch * 8;
    #pragma unroll
    for (int j = 0; j < 4; j++)
        CP16(base + ATT_SP + (uint32_t)(r8 + 32 * j) * ARS + ch * 16,
             qsrc + (size_t)(32 * j) * C3);
    CP_COMMIT();

    const __half* ksrc = qkv + (size_t)r8 * C3 + CDIM     + h * HDIM + ch * 8;
    const __half* vsrc = qkv + (size_t)r8 * C3 + 2 * CDIM + h * HDIM + ch * 8;

    // --- Prefetch KV tile 0 ---
    #pragma unroll
    for (int j = 0; j < 2; j++) {
        CP16(base + ATT_K(0) + (uint32_t)(r8 + 32 * j) * ARS + ch * 16,
             ksrc + (size_t)(32 * j) * C3);
        CP16(base + ATT_V(0) + (uint32_t)(r8 + 32 * j) * ARS + ch * 16,
             vsrc + (size_t)(32 * j) * C3);
    }
    CP_COMMIT();

    CP_WAIT(1);
    __syncthreads();

    // --- Q fragments to registers ---
    unsigned aq[4][4];
    #pragma unroll
    for (int ks = 0; ks < 4; ks++)
        LDSM4(aq[ks][0], aq[ks][1], aq[ks][2], aq[ks][3],
              base + ATT_SP + (uint32_t)(warp * 16 + aRowL) * ARS
                            + (2u * ks + aChL) * 16);

    float o[8][4] = {};
    float mrun[2] = {-1e30f, -1e30f};
    float lrun[2] = {0.f, 0.f};
    const int rowA = qt * 128 + warp * 16 + g;
    const int qmax = qt * 128 + warp * 16 + 15;

    const int ntiles = 2 * qt + 2;
    for (int i = 0; i < ntiles; i++) {
        __syncthreads();
        if (i + 1 < ntiles) {
            const uint32_t kb = base + ATT_K((i + 1) & 1);
            const uint32_t vb = base + ATT_V((i + 1) & 1);
            const size_t roff = (size_t)(i + 1) * 64 * C3;
            #pragma unroll
            for (int j = 0; j < 2; j++) {
                CP16(kb + (uint32_t)(r8 + 32 * j) * ARS + ch * 16,
                     ksrc + roff + (size_t)(32 * j) * C3);
                CP16(vb + (uint32_t)(r8 + 32 * j) * ARS + ch * 16,
                     vsrc + roff + (size_t)(32 * j) * C3);
            }
            CP_COMMIT();
            CP_WAIT(1);
        } else {
            CP_WAIT(0);
        }
        __syncthreads();

        const int jbase = i * 64;
        if (jbase > qmax) continue;

        const uint32_t kb = base + ATT_K(i & 1);
        const uint32_t vb = base + ATT_V(i & 1);

        // S = Q @ K^T  (16 x 64 per warp; q pre-scaled -> S already in
        // exp2 domain)
        float s[8][4] = {};
        #pragma unroll
        for (int ks = 0; ks < 4; ks++) {
            unsigned bf[8][2];
            #pragma unroll
            for (int p = 0; p < 4; p++)
                LDSM4(bf[2 * p][0], bf[2 * p][1], bf[2 * p + 1][0], bf[2 * p + 1][1],
                      kb + (uint32_t)(p * 16 + bRowL) * ARS + (2u * ks + bChL) * 16);
            #pragma unroll
            for (int nt = 0; nt < 8; nt++)
                mma16(s[nt], aq[ks], bf[nt]);
        }

        if (i >= 2 * qt) {
            #pragma unroll
            for (int nt = 0; nt < 8; nt++) {
                const int c = jbase + nt * 8 + tg * 2;
                if (c     > rowA)     s[nt][0] = -1e30f;
                if (c + 1 > rowA)     s[nt][1] = -1e30f;
                if (c     > rowA + 8) s[nt][2] = -1e30f;
                if (c + 1 > rowA + 8) s[nt][3] = -1e30f;
            }
        }

        // online softmax (base-2)
        float mA = -1e30f, mB = -1e30f;
        #pragma unroll
        for (int nt = 0; nt < 8; nt++) {
            mA = fmaxf(mA, fmaxf(s[nt][0], s[nt][1]));
            mB = fmaxf(mB, fmaxf(s[nt][2], s[nt][3]));
        }
        mA = fmaxf(mA, __shfl_xor_sync(0xffffffffu, mA, 1));
        mA = fmaxf(mA, __shfl_xor_sync(0xffffffffu, mA, 2));
        mB = fmaxf(mB, __shfl_xor_sync(0xffffffffu, mB, 1));
        mB = fmaxf(mB, __shfl_xor_sync(0xffffffffu, mB, 2));

        const float mnA = fmaxf(mrun[0], mA);
        const float mnB = fmaxf(mrun[1], mB);
        const float cA  = exp2f(mrun[0] - mnA);
        const float cB  = exp2f(mrun[1] - mnB);

        float sumA = 0.f, sumB = 0.f;
        unsigned ph[8][2];      // P in fp16 A-operand pairs
        #pragma unroll
        for (int nt = 0; nt < 8; nt++) {
            const float p0 = exp2f(s[nt][0] - mnA);
            const float p1 = exp2f(s[nt][1] - mnA);
            const float p2 = exp2f(s[nt][2] - mnB);
            const float p3 = exp2f(s[nt][3] - mnB);
            sumA += p0 + p1;
            sumB += p2 + p3;
            ph[nt][0] = h2u(p0, p1);
            ph[nt][1] = h2u(p2, p3);
            o[nt][0] *= cA; o[nt][1] *= cA;
            o[nt][2] *= cB; o[nt][3] *= cB;
        }
        sumA += __shfl_xor_sync(0xffffffffu, sumA, 1);
        sumA += __shfl_xor_sync(0xffffffffu, sumA, 2);
        sumB += __shfl_xor_sync(0xffffffffu, sumB, 1);
        sumB += __shfl_xor_sync(0xffffffffu, sumB, 2);
        lrun[0] = lrun[0] * cA + sumA;
        lrun[1] = lrun[1] * cB + sumB;
        mrun[0] = mnA;
        mrun[1] = mnB;

        // O += P @ V  (A = repacked S fragments; B via ldmatrix.trans of V)
        #pragma unroll
        for (int ks = 0; ks < 4; ks++) {
            const unsigned af[4] = { ph[2 * ks][0], ph[2 * ks][1],
                                     ph[2 * ks + 1][0], ph[2 * ks + 1][1] };
            unsigned bf[8][2];
            #pragma unroll
            for (int p = 0; p < 4; p++)
                LDSM4T(bf[2 * p][0], bf[2 * p][1], bf[2 * p + 1][0], bf[2 * p + 1][1],
                       vb + (uint32_t)(16 * ks + aRowL) * ARS + (2u * p + aChL) * 16);
            #pragma unroll
            for (int nt = 0; nt < 8; nt++)
                mma16(o[nt], af, bf[nt]);
        }
    }

    // epilogue: normalize, store fp16 y
    const float iA = 1.f / lrun[0];
    const float iB = 1.f / lrun[1];
    #pragma unroll
    for (int nt = 0; nt < 8; nt++) {
        const int col = h * HDIM + nt * 8 + tg * 2;
        *(__half2*)&g_y[(size_t)(b * SEQ + rowA) * CDIM + col] =
            __floats2half2_rn(o[nt][0] * iA, o[nt][1] * iA);
        *(__half2*)&g_y[(size_t)(b * SEQ + rowA + 8) * CDIM + col] =
            __floats2half2_rn(o[nt][2] * iB, o[nt][3] * iB);
    }
}

// ---------------------------------------------------------------------------
// Launch
// ---------------------------------------------------------------------------
extern "C" void kernel_launch(void* const* d_in, const int* in_sizes, int n_in,
                              void* d_out, int out_size)
{
    const float* x      = (const float*)d_in[0];  // [B,T,C]
    const float* W_attn = (const float*)d_in[1];  // [C,3C]
    const float* b_attn = (const float*)d_in[2];  // [3C]
    const float* W_proj = (const float*)d_in[3];  // [C,C]
    const float* b_proj = (const float*)d_in[4];  // [C]
    float* out = (float*)d_out;                   // [B,T,C]

    __half *qkv, *y, *xh, *wah, *wph;
    cudaGetSymbolAddress((void**)&qkv, g_qkv);
    cudaGetSymbolAddress((void**)&y,   g_y);
    cudaGetSymbolAddress((void**)&xh,  g_xh);
    cudaGetSymbolAddress((void**)&wah, g_wah);
    cudaGetSymbolAddress((void**)&wph, g_wph);

    cudaFuncSetAttribute(attn_h, cudaFuncAttributeMaxDynamicSharedMemorySize, ATT_SMEM);
    cudaFuncSetAttribute(gemm_h<QKV_BN>, cudaFuncAttributeMaxDynamicSharedMemorySize, QKV_SMEM);
    cudaFuncSetAttribute(gemm_h<PRJ_BN>, cudaFuncAttributeMaxDynamicSharedMemorySize, PRJ_SMEM);

    // 0) Preprocess: convert x, transpose+convert weights
    tohalf_pass<<<(BT * CDIM) / (4 * 256), 256>>>(x, xh);
    wtrans<<<dim3(C3 / 32, CDIM / 32), dim3(32, 8)>>>(W_attn, wah, CDIM, C3);
    wtrans<<<dim3(CDIM / 32, CDIM / 32), dim3(32, 8)>>>(W_proj, wph, CDIM, CDIM);

    // 1) QKV projection -> fp16 qkv (q columns pre-scaled by 0.125*log2e)
    gemm_h<QKV_BN><<<dim3(C3 / QKV_BN, BT / BM), 256, QKV_SMEM>>>(
        xh, wah, b_attn, qkv, BT, C3, CDIM, 1, 1);

    // 2) Causal flash attention -> fp16 y
    attn_h<<<dim3(SEQ / 128, HEADS, BATCH), 256, ATT_SMEM>>>();

    // 3) Output projection -> fp32 out
    gemm_h<PRJ_BN><<<dim3(CDIM / PRJ_BN, BT / BM), 256, PRJ_SMEM>>>(
        y, wph, b_proj, out, BT, CDIM, CDIM, 0, 0);
}

// round 16
// speedup vs baseline: 1.1333x; 1.0056x over previous
#include <cuda_runtime.h>
#include <cuda_fp16.h>
#include <cstdint>

// Problem constants
#define BATCH 4
#define SEQ   2048
#define CDIM  1024
#define HEADS 16
#define HDIM  64
#define BT    (BATCH * SEQ)       // 8192 rows
#define C3    (3 * CDIM)          // 3072

#define SCL2E 0.1803368801111204f // 0.125 * log2(e), folded into q at QKV epilogue

// Scratch in device globals (no dynamic allocation allowed)
__device__ __half g_qkv[(size_t)BT * C3];     // [B*T, 3C] fp16 (q pre-scaled)
__device__ __half g_y[(size_t)BT * CDIM];     // [B*T, C] attn out, fp16
__device__ __half g_xh[(size_t)BT * CDIM];    // x in fp16
__device__ __half g_wah[(size_t)C3 * CDIM];   // W_attn^T [3C][C] fp16
__device__ __half g_wph[(size_t)CDIM * CDIM]; // W_proj^T [C][C] fp16

// ---------------------------------------------------------------------------
// Helpers
// ---------------------------------------------------------------------------
__device__ __forceinline__ uint32_t smem_u32(const void* p) {
    uint32_t a;
    asm("{ .reg .u64 t; cvta.to.shared.u64 t, %1; cvt.u32.u64 %0, t; }"
        : "=r"(a) : "l"(p));
    return a;
}

__device__ __forceinline__ void mma16(float* c, const unsigned* a, const unsigned* b) {
    asm volatile(
        "mma.sync.aligned.m16n8k16.row.col.f32.f16.f16.f32 "
        "{%0,%1,%2,%3}, {%4,%5,%6,%7}, {%8,%9}, {%0,%1,%2,%3};"
        : "+f"(c[0]), "+f"(c[1]), "+f"(c[2]), "+f"(c[3])
        : "r"(a[0]), "r"(a[1]), "r"(a[2]), "r"(a[3]), "r"(b[0]), "r"(b[1]));
}

__device__ __forceinline__ unsigned h2u(float a, float b) {
    const __half2 h = __floats2half2_rn(a, b);
    return *(const unsigned*)&h;
}

#define LDSM4(r0, r1, r2, r3, addr)                                           \
    asm volatile("ldmatrix.sync.aligned.m8n8.x4.shared.b16 {%0,%1,%2,%3}, [%4];" \
                 : "=r"(r0), "=r"(r1), "=r"(r2), "=r"(r3) : "r"(addr))

#define LDSM4T(r0, r1, r2, r3, addr)                                          \
    asm volatile("ldmatrix.sync.aligned.m8n8.x4.trans.shared.b16 {%0,%1,%2,%3}, [%4];" \
                 : "=r"(r0), "=r"(r1), "=r"(r2), "=r"(r3) : "r"(addr))

#define CP16(dst, src)                                                        \
    asm volatile("cp.async.cg.shared.global [%0], [%1], 16;"                  \
                 :: "r"(dst), "l"(src))
#define CP_COMMIT() asm volatile("cp.async.commit_group;" ::: "memory")
#define CP_WAIT(n)  asm volatile("cp.async.wait_group %0;" :: "n"(n) : "memory")

// ---------------------------------------------------------------------------
// Preprocessing: fp16 convert (and transpose for weights)
// ---------------------------------------------------------------------------
__global__ void tohalf_pass(const float* __restrict__ src, __half* __restrict__ dst) {
    const int i = blockIdx.x * blockDim.x + threadIdx.x;
    const float4 v = ((const float4*)src)[i];
    ((__half2*)dst)[2 * i + 0] = __floats2half2_rn(v.x, v.y);
    ((__half2*)dst)[2 * i + 1] = __floats2half2_rn(v.z, v.w);
}

// W[K][N] -> WT[N][K] in fp16
__global__ void wtrans(const float* __restrict__ W, __half* __restrict__ WT,
                       int K, int N) {
    __shared__ float t[32][33];
    const int n0 = blockIdx.x * 32, k0 = blockIdx.y * 32;
    const int tx = threadIdx.x, ty = threadIdx.y;
    #pragma unroll
    for (int j = 0; j < 4; j++)
        t[ty + 8 * j][tx] = W[(size_t)(k0 + ty + 8 * j) * N + n0 + tx];
    __syncthreads();
    #pragma unroll
    for (int j = 0; j < 4; j++)
        WT[(size_t)(n0 + ty + 8 * j) * K + k0 + tx] = __float2half_rn(t[tx][ty + 8 * j]);
}

// ---------------------------------------------------------------------------
// FP16 GEMM (templated on BN): C[M,N] = A[M,K] @ Bt[N,K]^T + bias[N]
// Block tile 128 x BN_T, K-chunk 64, 256 threads = 8 warps (2x4),
// warp tile 64 x (BN_T/4). cp.async 4-stage pipeline, ldmatrix, XOR swizzle.
// scaleQ: multiply output columns < CDIM by SCL2E (QKV call only).
// ---------------------------------------------------------------------------
#define BM 128

template <int BN_T>
__global__ __launch_bounds__(256, 1) void gemm_h(
    const __half* __restrict__ A, const __half* __restrict__ Bt,
    const float* __restrict__ bias, void* __restrict__ Cout,
    int M, int N, int K, int outHalf, int scaleQ)
{
    constexpr int WN     = BN_T / 4;        // warp N tile (16/48/64)
    constexpr int NT     = WN / 8;          // n fragments
    constexpr int PB     = (WN + 15) / 16;  // B ldmatrix iters
    constexpr int BLOADS = BN_T / 32;       // B cp.async iters
    constexpr int GSB    = 16384;           // A bytes per stage
    constexpr int STAGE  = GSB + BN_T * 128;

    extern __shared__ char sm[];
    const uint32_t sb = smem_u32(sm);
    const int tid  = threadIdx.x;
    const int lane = tid & 31;
    const int warp = tid >> 5;
    const int g    = lane >> 2;
    const int tg   = lane & 3;
    const int m0 = blockIdx.y * BM;
    const int n0 = blockIdx.x * BN_T;
    const int wm = (warp >> 2) * 64;
    const int wn = (warp & 3) * WN;

    const int ar  = tid >> 3;
    const int ach = tid & 7;
    const uint32_t sca = (uint32_t)((ach ^ (ar & 7)) * 16);
    const __half* aSrc = A  + (size_t)(m0 + ar) * K + ach * 8;
    const __half* bSrc = Bt + (size_t)(n0 + ar) * K + ach * 8;

    const uint32_t alr = lane & 7;
    const uint32_t aRowL = (lane & 7) + ((lane >> 3) & 1) * 8;
    const uint32_t aChL  = (lane >> 4);
    const uint32_t bRowL = (lane & 7) + ((lane >> 4) & 1) * 8;
    const uint32_t bChL  = (lane >> 3) & 1;

    float acc[4][NT][4] = {};
    const int nch = K / 64;

    #pragma unroll
    for (int s = 0; s < 3; s++) {
        const uint32_t st = sb + s * STAGE;
        const int k0 = s * 64;
        #pragma unroll
        for (int j = 0; j < 4; j++)
            CP16(st + (uint32_t)(ar + 32 * j) * 128 + sca,
                 aSrc + k0 + (size_t)j * 32 * K);
        #pragma unroll
        for (int j = 0; j < BLOADS; j++)
            CP16(st + GSB + (uint32_t)(ar + 32 * j) * 128 + sca,
                 bSrc + k0 + (size_t)j * 32 * K);
        CP_COMMIT();
    }

    for (int i = 0; i < nch; i++) {
        CP_WAIT(2);
        __syncthreads();

        if (i + 3 < nch) {
            const uint32_t st = sb + ((i + 3) & 3) * STAGE;
            const int k0 = (i + 3) * 64;
            #pragma unroll
            for (int j = 0; j < 4; j++)
                CP16(st + (uint32_t)(ar + 32 * j) * 128 + sca,
                     aSrc + k0 + (size_t)j * 32 * K);
            #pragma unroll
            for (int j = 0; j < BLOADS; j++)
                CP16(st + GSB + (uint32_t)(ar + 32 * j) * 128 + sca,
                     bSrc + k0 + (size_t)j * 32 * K);
        }
        CP_COMMIT();

        const uint32_t stA = sb + (i & 3) * STAGE;
        const uint32_t stB = stA + GSB;
        #pragma unroll
        for (int ks = 0; ks < 4; ks++) {
            unsigned af[4][4];
            #pragma unroll
            for (int mt = 0; mt < 4; mt++) {
                const uint32_t addr = stA
                    + (uint32_t)(wm + mt * 16 + aRowL) * 128
                    + (((2u * ks + aChL) ^ alr) * 16);
                LDSM4(af[mt][0], af[mt][1], af[mt][2], af[mt][3], addr);
            }
            unsigned bf[NT][2];
            #pragma unroll
            for (int p = 0; p < PB; p++) {
                const uint32_t addr = stB
                    + (uint32_t)(wn + p * 16 + bRowL) * 128
                    + (((2u * ks + bChL) ^ alr) * 16);
                LDSM4(bf[2 * p][0], bf[2 * p][1], bf[2 * p + 1][0], bf[2 * p + 1][1], addr);
            }
            #pragma unroll
            for (int mt = 0; mt < 4; mt++)
                #pragma unroll
                for (int nt = 0; nt < NT; nt++)
                    mma16(acc[mt][nt], af[mt], bf[nt]);
        }
    }

    #pragma unroll
    for (int mt = 0; mt < 4; mt++) {
        const int r0 = m0 + wm + mt * 16 + g;
        #pragma unroll
        for (int nt = 0; nt < NT; nt++) {
            const int c0 = n0 + wn + nt * 8 + tg * 2;
            const float qs = (scaleQ && (n0 + wn + nt * 8) < CDIM) ? SCL2E : 1.0f;
            const float b0v = bias[c0], b1v = bias[c0 + 1];
            const float v0 = (acc[mt][nt][0] + b0v) * qs;
            const float v1 = (acc[mt][nt][1] + b1v) * qs;
            const float v2 = (acc[mt][nt][2] + b0v) * qs;
            const float v3 = (acc[mt][nt][3] + b1v) * qs;
            if (outHalf) {
                __half* Ch = (__half*)Cout;
                *(__half2*)&Ch[(size_t)r0 * N + c0] = __floats2half2_rn(v0, v1);
                *(__half2*)&Ch[(size_t)(r0 + 8) * N + c0] = __floats2half2_rn(v2, v3);
            } else {
                float* Cf = (float*)Cout;
                *(float2*)&Cf[(size_t)r0 * N + c0] = make_float2(v0, v1);
                *(float2*)&Cf[(size_t)(r0 + 8) * N + c0] = make_float2(v2, v3);
            }
        }
    }
}

#define QKV_BN   192
#define QKV_SMEM (4 * (16384 + QKV_BN * 128))  // 163840
#define PRJ_BN   64
#define PRJ_SMEM (4 * (16384 + PRJ_BN * 128))  // 98304

// ---------------------------------------------------------------------------
// Flash attention (causal), fp16 mma.sync, cp.async pipelined.
// Block = (128-row Q tile, head, batch). 256 threads = 8 warps.
// q arrives pre-scaled by 0.125*log2(e); softmax in exp2 domain.
// P stays in registers (S-frag -> A-frag repack). 2 CTAs/SM.
// KV tiles in a 3-deep ring -> ONE __syncthreads per tile:
//   buf (i+1)%3 was last consumed at tile i-2, ordered by iter i-1's barrier.
// ---------------------------------------------------------------------------
#define ARS 144                         // attention smem row stride bytes
#define ATT_SP   0                      // Q staging [128][144B] = 18432
#define ATT_K(s) (18432 + (s) * 18432)
#define ATT_V(s) (18432 + (s) * 18432 + 9216)
#define ATT_SMEM (18432 + 3 * 18432)    // 73728

__global__ __launch_bounds__(256, 2) void attn_h()
{
    extern __shared__ char attsm[];
    const uint32_t base = smem_u32(attsm);

    const int tid  = threadIdx.x;
    const int lane = tid & 31;
    const int warp = tid >> 5;
    const int g    = lane >> 2;
    const int tg   = lane & 3;

    const uint32_t aRowL = (lane & 7) + ((lane >> 3) & 1) * 8;
    const uint32_t aChL  = (lane >> 4);
    const uint32_t bRowL = (lane & 7) + ((lane >> 4) & 1) * 8;
    const uint32_t bChL  = (lane >> 3) & 1;

    const int qt = (gridDim.x - 1) - blockIdx.x;   // big tiles first
    const int h  = blockIdx.y;
    const int b  = blockIdx.z;
    const __half* qkv = g_qkv + (size_t)b * SEQ * C3;

    const int r8 = tid >> 3;            // 0..31
    const int ch = tid & 7;             // 0..7

    // --- Load Q (128 rows, pre-scaled) ---
    const __half* qsrc = qkv + (size_t)(qt * 128 + r8) * C3 + h * HDIM + ch * 8;
    #pragma unroll
    for (int j = 0; j < 4; j++)
        CP16(base + ATT_SP + (uint32_t)(r8 + 32 * j) * ARS + ch * 16,
             qsrc + (size_t)(32 * j) * C3);
    CP_COMMIT();

    const __half* ksrc = qkv + (size_t)r8 * C3 + CDIM     + h * HDIM + ch * 8;
    const __half* vsrc = qkv + (size_t)r8 * C3 + 2 * CDIM + h * HDIM + ch * 8;

    // --- Prefetch KV tile 0 into ring slot 0 ---
    #pragma unroll
    for (int j = 0; j < 2; j++) {
        CP16(base + ATT_K(0) + (uint32_t)(r8 + 32 * j) * ARS + ch * 16,
             ksrc + (size_t)(32 * j) * C3);
        CP16(base + ATT_V(0) + (uint32_t)(r8 + 32 * j) * ARS + ch * 16,
             vsrc + (size_t)(32 * j) * C3);
    }
    CP_COMMIT();

    CP_WAIT(1);          // Q arrived (tile 0 may still be in flight)
    __syncthreads();

    // --- Q fragments to registers ---
    unsigned aq[4][4];
    #pragma unroll
    for (int ks = 0; ks < 4; ks++)
        LDSM4(aq[ks][0], aq[ks][1], aq[ks][2], aq[ks][3],
              base + ATT_SP + (uint32_t)(warp * 16 + aRowL) * ARS
                            + (2u * ks + aChL) * 16);

    float o[8][4] = {};
    float mrun[2] = {-1e30f, -1e30f};
    float lrun[2] = {0.f, 0.f};
    const int rowA = qt * 128 + warp * 16 + g;
    const int qmax = qt * 128 + warp * 16 + 15;

    const int ntiles = 2 * qt + 2;
    int slot = 0, nslot = 1;
    for (int i = 0; i < ntiles; i++) {
        // prefetch tile i+1 into ring slot (i+1)%3
        if (i + 1 < ntiles) {
            const uint32_t kb = base + ATT_K(nslot);
            const uint32_t vb = base + ATT_V(nslot);
            const size_t roff = (size_t)(i + 1) * 64 * C3;
            #pragma unroll
            for (int j = 0; j < 2; j++) {
                CP16(kb + (uint32_t)(r8 + 32 * j) * ARS + ch * 16,
                     ksrc + roff + (size_t)(32 * j) * C3);
                CP16(vb + (uint32_t)(r8 + 32 * j) * ARS + ch * 16,
                     vsrc + roff + (size_t)(32 * j) * C3);
            }
            CP_COMMIT();
            CP_WAIT(1);         // tile i arrived; tile i+1 still in flight
        } else {
            CP_COMMIT();        // empty group
            CP_WAIT(1);         // tile i (last) arrived
        }
        __syncthreads();        // publish tile i; orders slot reuse (see hdr)

        const int jbase = i * 64;
        if (jbase <= qmax) {
            const uint32_t kb = base + ATT_K(slot);
            const uint32_t vb = base + ATT_V(slot);

            // S = Q @ K^T  (16 x 64 per warp; S already in exp2 domain)
            float s[8][4] = {};
            #pragma unroll
            for (int ks = 0; ks < 4; ks++) {
                unsigned bf[8][2];
                #pragma unroll
                for (int p = 0; p < 4; p++)
                    LDSM4(bf[2 * p][0], bf[2 * p][1], bf[2 * p + 1][0], bf[2 * p + 1][1],
                          kb + (uint32_t)(p * 16 + bRowL) * ARS + (2u * ks + bChL) * 16);
                #pragma unroll
                for (int nt = 0; nt < 8; nt++)
                    mma16(s[nt], aq[ks], bf[nt]);
            }

            if (i >= 2 * qt) {
                #pragma unroll
                for (int nt = 0; nt < 8; nt++) {
                    const int c = jbase + nt * 8 + tg * 2;
                    if (c     > rowA)     s[nt][0] = -1e30f;
                    if (c + 1 > rowA)     s[nt][1] = -1e30f;
                    if (c     > rowA + 8) s[nt][2] = -1e30f;
                    if (c + 1 > rowA + 8) s[nt][3] = -1e30f;
                }
            }

            // online softmax (base-2)
            float mA = -1e30f, mB = -1e30f;
            #pragma unroll
            for (int nt = 0; nt < 8; nt++) {
                mA = fmaxf(mA, fmaxf(s[nt][0], s[nt][1]));
                mB = fmaxf(mB, fmaxf(s[nt][2], s[nt][3]));
            }
            mA = fmaxf(mA, __shfl_xor_sync(0xffffffffu, mA, 1));
            mA = fmaxf(mA, __shfl_xor_sync(0xffffffffu, mA, 2));
            mB = fmaxf(mB, __shfl_xor_sync(0xffffffffu, mB, 1));
            mB = fmaxf(mB, __shfl_xor_sync(0xffffffffu, mB, 2));

            const float mnA = fmaxf(mrun[0], mA);
            const float mnB = fmaxf(mrun[1], mB);
            const float cA  = exp2f(mrun[0] - mnA);
            const float cB  = exp2f(mrun[1] - mnB);

            float sumA = 0.f, sumB = 0.f;
            unsigned ph[8][2];      // P in fp16 A-operand pairs
            #pragma unroll
            for (int nt = 0; nt < 8; nt++) {
                const float p0 = exp2f(s[nt][0] - mnA);
                const float p1 = exp2f(s[nt][1] - mnA);
                const float p2 = exp2f(s[nt][2] - mnB);
                const float p3 = exp2f(s[nt][3] - mnB);
                sumA += p0 + p1;
                sumB += p2 + p3;
                ph[nt][0] = h2u(p0, p1);
                ph[nt][1] = h2u(p2, p3);
                o[nt][0] *= cA; o[nt][1] *= cA;
                o[nt][2] *= cB; o[nt][3] *= cB;
            }
            sumA += __shfl_xor_sync(0xffffffffu, sumA, 1);
            sumA += __shfl_xor_sync(0xffffffffu, sumA, 2);
            sumB += __shfl_xor_sync(0xffffffffu, sumB, 1);
            sumB += __shfl_xor_sync(0xffffffffu, sumB, 2);
            lrun[0] = lrun[0] * cA + sumA;
            lrun[1] = lrun[1] * cB + sumB;
            mrun[0] = mnA;
            mrun[1] = mnB;

            // O += P @ V  (A = repacked S frags; B via ldmatrix.trans of V)
            #pragma unroll
            for (int ks = 0; ks < 4; ks++) {
                const unsigned af[4] = { ph[2 * ks][0], ph[2 * ks][1],
                                         ph[2 * ks + 1][0], ph[2 * ks + 1][1] };
                unsigned bf[8][2];
                #pragma unroll
                for (int p = 0; p < 4; p++)
                    LDSM4T(bf[2 * p][0], bf[2 * p][1], bf[2 * p + 1][0], bf[2 * p + 1][1],
                           vb + (uint32_t)(16 * ks + aRowL) * ARS + (2u * p + aChL) * 16);
                #pragma unroll
                for (int nt = 0; nt < 8; nt++)
                    mma16(o[nt], af, bf[nt]);
            }
        }

        slot = nslot;
        nslot = (nslot == 2) ? 0 : nslot + 1;
    }

    // epilogue: normalize, store fp16 y
    const float iA = 1.f / lrun[0];
    const float iB = 1.f / lrun[1];
    #pragma unroll
    for (int nt = 0; nt < 8; nt++) {
        const int col = h * HDIM + nt * 8 + tg * 2;
        *(__half2*)&g_y[(size_t)(b * SEQ + rowA) * CDIM + col] =
            __floats2half2_rn(o[nt][0] * iA, o[nt][1] * iA);
        *(__half2*)&g_y[(size_t)(b * SEQ + rowA + 8) * CDIM + col] =
            __floats2half2_rn(o[nt][2] * iB, o[nt][3] * iB);
    }
}

// ---------------------------------------------------------------------------
// Launch
// ---------------------------------------------------------------------------
extern "C" void kernel_launch(void* const* d_in, const int* in_sizes, int n_in,
                              void* d_out, int out_size)
{
    const float* x      = (const float*)d_in[0];  // [B,T,C]
    const float* W_attn = (const float*)d_in[1];  // [C,3C]
    const float* b_attn = (const float*)d_in[2];  // [3C]
    const float* W_proj = (const float*)d_in[3];  // [C,C]
    const float* b_proj = (const float*)d_in[4];  // [C]
    float* out = (float*)d_out;                   // [B,T,C]

    __half *qkv, *y, *xh, *wah, *wph;
    cudaGetSymbolAddress((void**)&qkv, g_qkv);
    cudaGetSymbolAddress((void**)&y,   g_y);
    cudaGetSymbolAddress((void**)&xh,  g_xh);
    cudaGetSymbolAddress((void**)&wah, g_wah);
    cudaGetSymbolAddress((void**)&wph, g_wph);

    cudaFuncSetAttribute(attn_h, cudaFuncAttributeMaxDynamicSharedMemorySize, ATT_SMEM);
    cudaFuncSetAttribute(gemm_h<QKV_BN>, cudaFuncAttributeMaxDynamicSharedMemorySize, QKV_SMEM);
    cudaFuncSetAttribute(gemm_h<PRJ_BN>, cudaFuncAttributeMaxDynamicSharedMemorySize, PRJ_SMEM);

    // 0) Preprocess: convert x, transpose+convert weights
    tohalf_pass<<<(BT * CDIM) / (4 * 256), 256>>>(x, xh);
    wtrans<<<dim3(C3 / 32, CDIM / 32), dim3(32, 8)>>>(W_attn, wah, CDIM, C3);
    wtrans<<<dim3(CDIM / 32, CDIM / 32), dim3(32, 8)>>>(W_proj, wph, CDIM, CDIM);

    // 1) QKV projection -> fp16 qkv (q columns pre-scaled by 0.125*log2e)
    gemm_h<QKV_BN><<<dim3(C3 / QKV_BN, BT / BM), 256, QKV_SMEM>>>(
        xh, wah, b_attn, qkv, BT, C3, CDIM, 1, 1);

    // 2) Causal flash attention -> fp16 y
    attn_h<<<dim3(SEQ / 128, HEADS, BATCH), 256, ATT_SMEM>>>();

    // 3) Output projection -> fp32 out (BN=64: 1024 CTAs -> 6.92 waves)
    gemm_h<PRJ_BN><<<dim3(CDIM / PRJ_BN, BT / BM), 256, PRJ_SMEM>>>(
        y, wph, b_proj, out, BT, CDIM, CDIM, 0, 0);
}